// round 14
// baseline (speedup 1.0000x reference)
#include <cuda_runtime.h>
#include <math.h>

#define NQ       12
#define DEPTH    4
#define DIM      4096
#define NTHREADS 256

// XOR swizzle for conflict-free float2 shared accesses
__device__ __forceinline__ int swz(int e) { return e ^ ((e >> 4) & 15); }

// Composed CNOT-ladder gather: s_after[i] = s_before[gperm(i)].
__device__ __forceinline__ int gperm(int j) {
    j ^= (j & 1) << 11;                 // m = 11
    #pragma unroll
    for (int m = 10; m >= 0; --m)
        j ^= ((j >> (11 - m)) & 1) << (10 - m);
    return j;
}

// Apply fused 2x2 complex gate (g = u00r,u00i,u01r,u01i,u10r,u10i,u11r,u11i)
// to register-local bit k of the 16-amp register file.
__device__ __forceinline__ void apply_gate(float re[16], float im[16],
                                           const float* __restrict__ g, int k) {
    const float u00r = g[0], u00i = g[1], u01r = g[2], u01i = g[3];
    const float u10r = g[4], u10i = g[5], u11r = g[6], u11i = g[7];
    const int m = 1 << k;
    #pragma unroll
    for (int r0 = 0; r0 < 16; ++r0) {
        if (r0 & m) continue;
        const int r1 = r0 | m;
        const float a0r = re[r0], a0i = im[r0];
        const float a1r = re[r1], a1i = im[r1];
        re[r0] = u00r * a0r - u00i * a0i + u01r * a1r - u01i * a1i;
        im[r0] = u00r * a0i + u00i * a0r + u01r * a1i + u01i * a1r;
        re[r1] = u10r * a0r - u10i * a0i + u11r * a1r - u11i * a1i;
        im[r1] = u10r * a0i + u10i * a0r + u11r * a1i + u11i * a1r;
    }
}

// Same gate, purely real input state (im == 0 at layer-0 entry): half the FMAs.
__device__ __forceinline__ void apply_gate_real(float re[16], float im[16],
                                                const float* __restrict__ g, int k) {
    const float u00r = g[0], u00i = g[1], u01r = g[2], u01i = g[3];
    const float u10r = g[4], u10i = g[5], u11r = g[6], u11i = g[7];
    const int m = 1 << k;
    #pragma unroll
    for (int r0 = 0; r0 < 16; ++r0) {
        if (r0 & m) continue;
        const int r1 = r0 | m;
        const float a0r = re[r0], a1r = re[r1];
        re[r0] = u00r * a0r + u01r * a1r;
        im[r0] = u00i * a0r + u01i * a1r;
        re[r1] = u10r * a0r + u11r * a1r;
        im[r1] = u10i * a0r + u11i * a1r;
    }
}

__global__ void __launch_bounds__(NTHREADS)
qsim_kernel(const float* __restrict__ input,
            const float* __restrict__ ax,
            const float* __restrict__ ay,
            const float* __restrict__ az,
            float* __restrict__ out)
{
    __shared__ float2 sAmp[DIM];              // 32 KB state exchange buffer
    __shared__ float  sGates[DEPTH * NQ * 8]; // 48 fused gates, 8 floats each
    __shared__ float  sRed[16];               // block reduction scratch

    const int tid = threadIdx.x;
    const int row = blockIdx.x;

    // ---- fused gate matrices U = Rz(l) * Ry(p) * Rx(t), one per (layer,qubit) ----
    if (tid < DEPTH * NQ) {
        float sx, cx, sy, cy, sz, cz;
        sincosf(0.5f * ax[tid], &sx, &cx);
        sincosf(0.5f * ay[tid], &sy, &cy);
        sincosf(0.5f * az[tid], &sz, &cz);
        // M = Ry*Rx
        const float m00r = cy * cx, m00i =  sy * sx;
        const float m01r = -sy * cx, m01i = -cy * sx;
        const float m10r =  sy * cx, m10i = -cy * sx;
        const float m11r =  cy * cx, m11i = -sy * sx;
        // row0 *= exp(-i l/2) = (cz, -sz); row1 *= exp(+i l/2) = (cz, +sz)
        float* g = &sGates[tid * 8];
        g[0] = cz * m00r + sz * m00i;  g[1] = cz * m00i - sz * m00r;
        g[2] = cz * m01r + sz * m01i;  g[3] = cz * m01i - sz * m01r;
        g[4] = cz * m10r - sz * m10i;  g[5] = cz * m10i + sz * m10r;
        g[6] = cz * m11r - sz * m11i;  g[7] = cz * m11i + sz * m11r;
    }

    // ---- load input row + amplitude encoding ----
    float mag[16];
    const float4* inrow = reinterpret_cast<const float4*>(input + (size_t)row * DIM);
    float s1 = 0.f, s2 = 0.f;
    #pragma unroll
    for (int k = 0; k < 4; ++k) {
        const float4 v = inrow[tid * 4 + k];
        const float a = fabsf(v.x), b = fabsf(v.y), c = fabsf(v.z), d = fabsf(v.w);
        mag[4 * k + 0] = a; mag[4 * k + 1] = b;
        mag[4 * k + 2] = c; mag[4 * k + 3] = d;
        s1 += (a + b) + (c + d);
        s2 += a * a + b * b + c * c + d * d;
    }
    #pragma unroll
    for (int o = 16; o > 0; o >>= 1) {
        s1 += __shfl_xor_sync(0xffffffffu, s1, o);
        s2 += __shfl_xor_sync(0xffffffffu, s2, o);
    }
    if ((tid & 31) == 0) { sRed[tid >> 5] = s1; sRed[8 + (tid >> 5)] = s2; }
    __syncthreads();   // also publishes sGates
    float S1 = 0.f, S2 = 0.f;
    #pragma unroll
    for (int w = 0; w < 8; ++w) { S1 += sRed[w]; S2 += sRed[8 + w]; }

    // state registers: thread t holds flat indices [t*16, t*16+16) (Layout0)
    float re[16], im[16];
    if (S1 > 1e-8f) {
        const float sc   = rsqrtf(S1);          // wn_i = |x_i| * sc
        const float norm = sqrtf(S2) * sc;      // sqrt(sum wn^2) = sqrt(S2/S1)
        const float fs   = (norm > 1e-8f) ? (sc / norm) : sc;
        #pragma unroll
        for (int r = 0; r < 16; ++r) { re[r] = mag[r] * fs; im[r] = 0.f; }
    } else {
        #pragma unroll
        for (int r = 0; r < 16; ++r) { re[r] = 0.015625f; im[r] = 0.f; } // 1/sqrt(4096)
    }

    const int t = tid;

    #pragma unroll 1
    for (int layer = 0; layer < DEPTH; ++layer) {
        const float* gl = &sGates[layer * NQ * 8];

        // ---- Stage A (Layout0): reg bit k == global bit k -> qubit 11-k ----
        if (layer == 0) {
            apply_gate_real(re, im, gl + 11 * 8, 0);   // state purely real at entry
        } else {
            apply_gate(re, im, gl + 11 * 8, 0);
        }
        #pragma unroll
        for (int k = 1; k < 4; ++k) apply_gate(re, im, gl + (11 - k) * 8, k);

        // ---- Layout0 -> Layout1 (global = t_hi:reg:t_lo) ----
        __syncthreads();
        #pragma unroll
        for (int r = 0; r < 16; ++r)
            sAmp[swz((t << 4) | r)] = make_float2(re[r], im[r]);
        __syncthreads();
        {
            const int base = ((t >> 4) << 8) | (t & 15);
            #pragma unroll
            for (int r = 0; r < 16; ++r) {
                const float2 v = sAmp[swz(base | (r << 4))];
                re[r] = v.x; im[r] = v.y;
            }
        }

        // ---- Stage B: reg bit k == global bit 4+k -> qubit 7-k ----
        #pragma unroll
        for (int k = 0; k < 4; ++k) apply_gate(re, im, gl + (7 - k) * 8, k);

        // ---- Layout1 -> Layout2 (global = reg:t) ----
        __syncthreads();
        {
            const int base = ((t >> 4) << 8) | (t & 15);
            #pragma unroll
            for (int r = 0; r < 16; ++r)
                sAmp[swz(base | (r << 4))] = make_float2(re[r], im[r]);
        }
        __syncthreads();
        #pragma unroll
        for (int r = 0; r < 16; ++r) {
            const float2 v = sAmp[swz((r << 8) | t)];
            re[r] = v.x; im[r] = v.y;
        }

        // ---- Stage C: reg bit k == global bit 8+k -> qubit 3-k ----
        #pragma unroll
        for (int k = 0; k < 4; ++k) apply_gate(re, im, gl + (3 - k) * 8, k);

        // ---- Layout2 -> Layout0 with the CNOT ladder folded into the gather ----
        __syncthreads();
        #pragma unroll
        for (int r = 0; r < 16; ++r)
            sAmp[swz((r << 8) | t)] = make_float2(re[r], im[r]);
        __syncthreads();
        #pragma unroll
        for (int r = 0; r < 16; ++r) {
            const float2 v = sAmp[swz(gperm((t << 4) | r))];
            re[r] = v.x; im[r] = v.y;
        }
    }

    // ---- measurement: |amplitude| ----
    float4* orow = reinterpret_cast<float4*>(out + (size_t)row * DIM);
    #pragma unroll
    for (int k = 0; k < 4; ++k) {
        float4 v;
        v.x = sqrtf(re[4 * k + 0] * re[4 * k + 0] + im[4 * k + 0] * im[4 * k + 0]);
        v.y = sqrtf(re[4 * k + 1] * re[4 * k + 1] + im[4 * k + 1] * im[4 * k + 1]);
        v.z = sqrtf(re[4 * k + 2] * re[4 * k + 2] + im[4 * k + 2] * im[4 * k + 2]);
        v.w = sqrtf(re[4 * k + 3] * re[4 * k + 3] + im[4 * k + 3] * im[4 * k + 3]);
        orow[tid * 4 + k] = v;
    }
}

extern "C" void kernel_launch(void* const* d_in, const int* in_sizes, int n_in,
                              void* d_out, int out_size) {
    const float* input = (const float*)d_in[0];
    const float* ax    = (const float*)d_in[1];
    const float* ay    = (const float*)d_in[2];
    const float* az    = (const float*)d_in[3];
    float* out = (float*)d_out;
    const int rows = in_sizes[0] / DIM;
    qsim_kernel<<<rows, NTHREADS>>>(input, ax, ay, az, out);
}

// round 15
// speedup vs baseline: 1.0346x; 1.0346x over previous
#include <cuda_runtime.h>
#include <math.h>

#define NQ       12
#define DEPTH    4
#define DIM      4096
#define NTHREADS 256

// XOR swizzle for conflict-free float2 shared accesses
__device__ __forceinline__ int swz(int e) { return e ^ ((e >> 4) & 15); }

// Composed CNOT-ladder gather: s_after[i] = s_before[gperm(i)].
__device__ __forceinline__ int gperm(int j) {
    j ^= (j & 1) << 11;                 // m = 11
    #pragma unroll
    for (int m = 10; m >= 0; --m)
        j ^= ((j >> (11 - m)) & 1) << (10 - m);
    return j;
}

// Apply fused 2x2 complex gate (g = u00r,u00i,u01r,u01i,u10r,u10i,u11r,u11i)
// to register-local bit k of the 16-amp register file.
__device__ __forceinline__ void apply_gate(float re[16], float im[16],
                                           const float* __restrict__ g, int k) {
    const float u00r = g[0], u00i = g[1], u01r = g[2], u01i = g[3];
    const float u10r = g[4], u10i = g[5], u11r = g[6], u11i = g[7];
    const int m = 1 << k;
    #pragma unroll
    for (int r0 = 0; r0 < 16; ++r0) {
        if (r0 & m) continue;
        const int r1 = r0 | m;
        const float a0r = re[r0], a0i = im[r0];
        const float a1r = re[r1], a1i = im[r1];
        re[r0] = u00r * a0r - u00i * a0i + u01r * a1r - u01i * a1i;
        im[r0] = u00r * a0i + u00i * a0r + u01r * a1i + u01i * a1r;
        re[r1] = u10r * a0r - u10i * a0i + u11r * a1r - u11i * a1i;
        im[r1] = u10r * a0i + u10i * a0r + u11r * a1i + u11i * a1r;
    }
}

__global__ void __launch_bounds__(NTHREADS)
qsim_kernel(const float* __restrict__ input,
            const float* __restrict__ ax,
            const float* __restrict__ ay,
            const float* __restrict__ az,
            float* __restrict__ out)
{
    __shared__ float2 sAmp[DIM];              // 32 KB state exchange buffer
    __shared__ float  sGates[DEPTH * NQ * 8]; // 48 fused gates, 8 floats each
    __shared__ float  sRed[16];               // block reduction scratch

    const int tid = threadIdx.x;
    const int row = blockIdx.x;

    // ---- fused gate matrices U = Rz(l) * Ry(p) * Rx(t), one per (layer,qubit) ----
    if (tid < DEPTH * NQ) {
        float sx, cx, sy, cy, sz, cz;
        sincosf(0.5f * ax[tid], &sx, &cx);
        sincosf(0.5f * ay[tid], &sy, &cy);
        sincosf(0.5f * az[tid], &sz, &cz);
        // M = Ry*Rx
        const float m00r = cy * cx, m00i =  sy * sx;
        const float m01r = -sy * cx, m01i = -cy * sx;
        const float m10r =  sy * cx, m10i = -cy * sx;
        const float m11r =  cy * cx, m11i = -sy * sx;
        // row0 *= exp(-i l/2) = (cz, -sz); row1 *= exp(+i l/2) = (cz, +sz)
        float* g = &sGates[tid * 8];
        g[0] = cz * m00r + sz * m00i;  g[1] = cz * m00i - sz * m00r;
        g[2] = cz * m01r + sz * m01i;  g[3] = cz * m01i - sz * m01r;
        g[4] = cz * m10r - sz * m10i;  g[5] = cz * m10i + sz * m10r;
        g[6] = cz * m11r - sz * m11i;  g[7] = cz * m11i + sz * m11r;
    }

    // ---- load input row + amplitude encoding ----
    float mag[16];
    const float4* inrow = reinterpret_cast<const float4*>(input + (size_t)row * DIM);
    float s1 = 0.f, s2 = 0.f;
    #pragma unroll
    for (int k = 0; k < 4; ++k) {
        const float4 v = inrow[tid * 4 + k];
        const float a = fabsf(v.x), b = fabsf(v.y), c = fabsf(v.z), d = fabsf(v.w);
        mag[4 * k + 0] = a; mag[4 * k + 1] = b;
        mag[4 * k + 2] = c; mag[4 * k + 3] = d;
        s1 += (a + b) + (c + d);
        s2 += a * a + b * b + c * c + d * d;
    }
    #pragma unroll
    for (int o = 16; o > 0; o >>= 1) {
        s1 += __shfl_xor_sync(0xffffffffu, s1, o);
        s2 += __shfl_xor_sync(0xffffffffu, s2, o);
    }
    if ((tid & 31) == 0) { sRed[tid >> 5] = s1; sRed[8 + (tid >> 5)] = s2; }
    __syncthreads();   // also publishes sGates
    float S1 = 0.f, S2 = 0.f;
    #pragma unroll
    for (int w = 0; w < 8; ++w) { S1 += sRed[w]; S2 += sRed[8 + w]; }

    // state registers: thread t holds flat indices [t*16, t*16+16) (Layout0)
    float re[16], im[16];
    if (S1 > 1e-8f) {
        const float sc   = rsqrtf(S1);          // wn_i = |x_i| * sc
        const float norm = sqrtf(S2) * sc;      // sqrt(sum wn^2) = sqrt(S2/S1)
        const float fs   = (norm > 1e-8f) ? (sc / norm) : sc;
        #pragma unroll
        for (int r = 0; r < 16; ++r) { re[r] = mag[r] * fs; im[r] = 0.f; }
    } else {
        #pragma unroll
        for (int r = 0; r < 16; ++r) { re[r] = 0.015625f; im[r] = 0.f; } // 1/sqrt(4096)
    }

    const int t = tid;

    #pragma unroll 1
    for (int layer = 0; layer < DEPTH; ++layer) {
        const float* gl = &sGates[layer * NQ * 8];

        // ---- Stage A (Layout0): reg bit k == global bit k -> qubit 11-k ----
        #pragma unroll
        for (int k = 0; k < 4; ++k) apply_gate(re, im, gl + (11 - k) * 8, k);

        // ---- Layout0 -> Layout1 (global = t_hi:reg:t_lo) ----
        // Region g = t>>4 (256 slots) is written and read ONLY by half-warp g,
        // but the previous layer's E3 gather read across all regions -> block barrier.
        __syncthreads();
        #pragma unroll
        for (int r = 0; r < 16; ++r)
            sAmp[swz((t << 4) | r)] = make_float2(re[r], im[r]);
        __syncwarp();   // E1 write->read is half-warp-local: warp sync suffices
        {
            const int base = ((t >> 4) << 8) | (t & 15);
            #pragma unroll
            for (int r = 0; r < 16; ++r) {
                const float2 v = sAmp[swz(base | (r << 4))];
                re[r] = v.x; im[r] = v.y;
            }
        }

        // ---- Stage B: reg bit k == global bit 4+k -> qubit 7-k ----
        #pragma unroll
        for (int k = 0; k < 4; ++k) apply_gate(re, im, gl + (7 - k) * 8, k);

        // ---- Layout1 -> Layout2 (global = reg:t) ----
        // E2 writes target exactly the slots this same thread read in E1
        // (bijective per-thread) -> no cross-thread hazard, no barrier needed.
        {
            const int base = ((t >> 4) << 8) | (t & 15);
            #pragma unroll
            for (int r = 0; r < 16; ++r)
                sAmp[swz(base | (r << 4))] = make_float2(re[r], im[r]);
        }
        __syncthreads();   // E2 read crosses regions: block barrier required
        #pragma unroll
        for (int r = 0; r < 16; ++r) {
            const float2 v = sAmp[swz((r << 8) | t)];
            re[r] = v.x; im[r] = v.y;
        }

        // ---- Stage C: reg bit k == global bit 8+k -> qubit 3-k ----
        #pragma unroll
        for (int k = 0; k < 4; ++k) apply_gate(re, im, gl + (3 - k) * 8, k);

        // ---- Layout2 -> Layout0 with the CNOT ladder folded into the gather ----
        // E3 writes target exactly the slots this same thread read in E2
        // (region r, offset t — unique to thread t) -> no barrier before writes.
        #pragma unroll
        for (int r = 0; r < 16; ++r)
            sAmp[swz((r << 8) | t)] = make_float2(re[r], im[r]);
        __syncthreads();   // gperm gather crosses all regions: block barrier required
        #pragma unroll
        for (int r = 0; r < 16; ++r) {
            const float2 v = sAmp[swz(gperm((t << 4) | r))];
            re[r] = v.x; im[r] = v.y;
        }
    }

    // ---- measurement: |amplitude| ----
    float4* orow = reinterpret_cast<float4*>(out + (size_t)row * DIM);
    #pragma unroll
    for (int k = 0; k < 4; ++k) {
        float4 v;
        v.x = sqrtf(re[4 * k + 0] * re[4 * k + 0] + im[4 * k + 0] * im[4 * k + 0]);
        v.y = sqrtf(re[4 * k + 1] * re[4 * k + 1] + im[4 * k + 1] * im[4 * k + 1]);
        v.z = sqrtf(re[4 * k + 2] * re[4 * k + 2] + im[4 * k + 2] * im[4 * k + 2]);
        v.w = sqrtf(re[4 * k + 3] * re[4 * k + 3] + im[4 * k + 3] * im[4 * k + 3]);
        orow[tid * 4 + k] = v;
    }
}

extern "C" void kernel_launch(void* const* d_in, const int* in_sizes, int n_in,
                              void* d_out, int out_size) {
    const float* input = (const float*)d_in[0];
    const float* ax    = (const float*)d_in[1];
    const float* ay    = (const float*)d_in[2];
    const float* az    = (const float*)d_in[3];
    float* out = (float*)d_out;
    const int rows = in_sizes[0] / DIM;
    qsim_kernel<<<rows, NTHREADS>>>(input, ax, ay, az, out);
}

// round 16
// speedup vs baseline: 1.0382x; 1.0035x over previous
#include <cuda_runtime.h>
#include <math.h>

#define NQ       12
#define DEPTH    4
#define DIM      4096
#define NTHREADS 256

// XOR swizzle for conflict-free float2 shared accesses
__device__ __forceinline__ int swz(int e) { return e ^ ((e >> 4) & 15); }

// Composed CNOT-ladder gather: s_after[i] = s_before[gperm(i)].
__device__ __forceinline__ int gperm(int j) {
    j ^= (j & 1) << 11;                 // m = 11
    #pragma unroll
    for (int m = 10; m >= 0; --m)
        j ^= ((j >> (11 - m)) & 1) << (10 - m);
    return j;
}

// Apply fused 2x2 complex gate to register-local bit k.
// Coefficients as two float4 (LDS.128): gA = (u00r,u00i,u01r,u01i), gB = (u10r,u10i,u11r,u11i).
// FMA expressions identical to the champion's.
__device__ __forceinline__ void apply_gate(float re[16], float im[16],
                                           const float4 gA, const float4 gB, int k) {
    const float u00r = gA.x, u00i = gA.y, u01r = gA.z, u01i = gA.w;
    const float u10r = gB.x, u10i = gB.y, u11r = gB.z, u11i = gB.w;
    const int m = 1 << k;
    #pragma unroll
    for (int r0 = 0; r0 < 16; ++r0) {
        if (r0 & m) continue;
        const int r1 = r0 | m;
        const float a0r = re[r0], a0i = im[r0];
        const float a1r = re[r1], a1i = im[r1];
        re[r0] = u00r * a0r - u00i * a0i + u01r * a1r - u01i * a1i;
        im[r0] = u00r * a0i + u00i * a0r + u01r * a1i + u01i * a1r;
        re[r1] = u10r * a0r - u10i * a0i + u11r * a1r - u11i * a1i;
        im[r1] = u10r * a0i + u10i * a0r + u11r * a1i + u11i * a1r;
    }
}

__global__ void __launch_bounds__(NTHREADS)
qsim_kernel(const float* __restrict__ input,
            const float* __restrict__ ax,
            const float* __restrict__ ay,
            const float* __restrict__ az,
            float* __restrict__ out)
{
    __shared__ float2 sAmp[DIM];               // 32 KB state exchange buffer
    __shared__ float4 sGates[DEPTH * NQ * 2];  // 48 fused gates, 2 float4 each (same bytes)
    __shared__ float  sRed[16];                // block reduction scratch

    const int tid = threadIdx.x;
    const int row = blockIdx.x;

    // ---- fused gate matrices U = Rz(l) * Ry(p) * Rx(t), one per (layer,qubit) ----
    if (tid < DEPTH * NQ) {
        float sx, cx, sy, cy, sz, cz;
        sincosf(0.5f * ax[tid], &sx, &cx);
        sincosf(0.5f * ay[tid], &sy, &cy);
        sincosf(0.5f * az[tid], &sz, &cz);
        // M = Ry*Rx
        const float m00r = cy * cx, m00i =  sy * sx;
        const float m01r = -sy * cx, m01i = -cy * sx;
        const float m10r =  sy * cx, m10i = -cy * sx;
        const float m11r =  cy * cx, m11i = -sy * sx;
        // row0 *= exp(-i l/2) = (cz, -sz); row1 *= exp(+i l/2) = (cz, +sz)
        sGates[tid * 2 + 0] = make_float4(cz * m00r + sz * m00i, cz * m00i - sz * m00r,
                                          cz * m01r + sz * m01i, cz * m01i - sz * m01r);
        sGates[tid * 2 + 1] = make_float4(cz * m10r - sz * m10i, cz * m10i + sz * m10r,
                                          cz * m11r - sz * m11i, cz * m11i + sz * m11r);
    }

    // ---- load input row + amplitude encoding ----
    float mag[16];
    const float4* inrow = reinterpret_cast<const float4*>(input + (size_t)row * DIM);
    float s1 = 0.f, s2 = 0.f;
    #pragma unroll
    for (int k = 0; k < 4; ++k) {
        const float4 v = inrow[tid * 4 + k];
        const float a = fabsf(v.x), b = fabsf(v.y), c = fabsf(v.z), d = fabsf(v.w);
        mag[4 * k + 0] = a; mag[4 * k + 1] = b;
        mag[4 * k + 2] = c; mag[4 * k + 3] = d;
        s1 += (a + b) + (c + d);
        s2 += a * a + b * b + c * c + d * d;
    }
    #pragma unroll
    for (int o = 16; o > 0; o >>= 1) {
        s1 += __shfl_xor_sync(0xffffffffu, s1, o);
        s2 += __shfl_xor_sync(0xffffffffu, s2, o);
    }
    if ((tid & 31) == 0) { sRed[tid >> 5] = s1; sRed[8 + (tid >> 5)] = s2; }
    __syncthreads();   // also publishes sGates
    float S1 = 0.f, S2 = 0.f;
    #pragma unroll
    for (int w = 0; w < 8; ++w) { S1 += sRed[w]; S2 += sRed[8 + w]; }

    // state registers: thread t holds flat indices [t*16, t*16+16) (Layout0)
    float re[16], im[16];
    if (S1 > 1e-8f) {
        const float sc   = rsqrtf(S1);          // wn_i = |x_i| * sc
        const float norm = sqrtf(S2) * sc;      // sqrt(sum wn^2) = sqrt(S2/S1)
        const float fs   = (norm > 1e-8f) ? (sc / norm) : sc;
        #pragma unroll
        for (int r = 0; r < 16; ++r) { re[r] = mag[r] * fs; im[r] = 0.f; }
    } else {
        #pragma unroll
        for (int r = 0; r < 16; ++r) { re[r] = 0.015625f; im[r] = 0.f; } // 1/sqrt(4096)
    }

    const int t = tid;

    #pragma unroll 1
    for (int layer = 0; layer < DEPTH; ++layer) {
        const float4* gl = &sGates[layer * NQ * 2];

        // ---- Stage A (Layout0): reg bit k == global bit k -> qubit 11-k ----
        apply_gate(re, im, gl[22], gl[23], 0);   // qubit 11
        apply_gate(re, im, gl[20], gl[21], 1);   // qubit 10
        apply_gate(re, im, gl[18], gl[19], 2);   // qubit 9
        apply_gate(re, im, gl[16], gl[17], 3);   // qubit 8

        // ---- Layout0 -> Layout1 (global = t_hi:reg:t_lo) ----
        __syncthreads();   // protects prior layer's E3 gather reads
        #pragma unroll
        for (int r = 0; r < 16; ++r)
            sAmp[swz((t << 4) | r)] = make_float2(re[r], im[r]);
        __syncwarp();      // E1 write->read is half-warp-local (R15-validated)
        {
            const int base = ((t >> 4) << 8) | (t & 15);
            #pragma unroll
            for (int r = 0; r < 16; ++r) {
                const float2 v = sAmp[swz(base | (r << 4))];
                re[r] = v.x; im[r] = v.y;
            }
        }

        // ---- Stage B: reg bit k == global bit 4+k -> qubit 7-k ----
        apply_gate(re, im, gl[14], gl[15], 0);   // qubit 7
        apply_gate(re, im, gl[12], gl[13], 1);   // qubit 6
        apply_gate(re, im, gl[10], gl[11], 2);   // qubit 5
        apply_gate(re, im, gl[ 8], gl[ 9], 3);   // qubit 4

        // ---- Layout1 -> Layout2 (global = reg:t) ----
        // E2 writes target this thread's own E1-read slots: no barrier needed (R15-validated)
        {
            const int base = ((t >> 4) << 8) | (t & 15);
            #pragma unroll
            for (int r = 0; r < 16; ++r)
                sAmp[swz(base | (r << 4))] = make_float2(re[r], im[r]);
        }
        __syncthreads();   // E2 read crosses regions
        #pragma unroll
        for (int r = 0; r < 16; ++r) {
            const float2 v = sAmp[swz((r << 8) | t)];
            re[r] = v.x; im[r] = v.y;
        }

        // ---- Stage C: reg bit k == global bit 8+k -> qubit 3-k ----
        apply_gate(re, im, gl[6], gl[7], 0);     // qubit 3
        apply_gate(re, im, gl[4], gl[5], 1);     // qubit 2
        apply_gate(re, im, gl[2], gl[3], 2);     // qubit 1
        apply_gate(re, im, gl[0], gl[1], 3);     // qubit 0

        // ---- Layout2 -> Layout0 with the CNOT ladder folded into the gather ----
        // E3 writes target this thread's own E2-read slots: no barrier needed (R15-validated)
        #pragma unroll
        for (int r = 0; r < 16; ++r)
            sAmp[swz((r << 8) | t)] = make_float2(re[r], im[r]);
        __syncthreads();   // gperm gather crosses all regions
        #pragma unroll
        for (int r = 0; r < 16; ++r) {
            const float2 v = sAmp[swz(gperm((t << 4) | r))];
            re[r] = v.x; im[r] = v.y;
        }
    }

    // ---- measurement: |amplitude| ----
    float4* orow = reinterpret_cast<float4*>(out + (size_t)row * DIM);
    #pragma unroll
    for (int k = 0; k < 4; ++k) {
        float4 v;
        v.x = sqrtf(re[4 * k + 0] * re[4 * k + 0] + im[4 * k + 0] * im[4 * k + 0]);
        v.y = sqrtf(re[4 * k + 1] * re[4 * k + 1] + im[4 * k + 1] * im[4 * k + 1]);
        v.z = sqrtf(re[4 * k + 2] * re[4 * k + 2] + im[4 * k + 2] * im[4 * k + 2]);
        v.w = sqrtf(re[4 * k + 3] * re[4 * k + 3] + im[4 * k + 3] * im[4 * k + 3]);
        orow[tid * 4 + k] = v;
    }
}

extern "C" void kernel_launch(void* const* d_in, const int* in_sizes, int n_in,
                              void* d_out, int out_size) {
    const float* input = (const float*)d_in[0];
    const float* ax    = (const float*)d_in[1];
    const float* ay    = (const float*)d_in[2];
    const float* az    = (const float*)d_in[3];
    float* out = (float*)d_out;
    const int rows = in_sizes[0] / DIM;
    qsim_kernel<<<rows, NTHREADS>>>(input, ax, ay, az, out);
}